// round 5
// baseline (speedup 1.0000x reference)
#include <cuda_runtime.h>

// LSTM autoencoder: T=1024, B=1024, IN=1, H=64
// Encoder: 256 blocks x 256 threads, BB=4 rows/block, 2 blocks/SM.
//   thread = gate column g; 65 scalar weights in regs; 4 scalar FFMA
//   accumulators; h[k][0..3] read as one broadcast LDS.128 per k.
//   (R2 finding: fma.rn.f32x2 gives no issue-rate win on sm_103a -> scalar FFMA.)
// Activations: MUFU.TANH (tanh.approx.f32), 1 MUFU each.

#define T_STEPS 1024
#define BATCH   1024
#define HID     64
#define GATES   256
#define BB      4          // batch rows per block

__device__ float g_henc[HID * BATCH];   // h_enc transposed: [k][b]

__device__ __forceinline__ float tanh_apx(float x) {
    float y;
    asm("tanh.approx.f32 %0, %1;" : "=f"(y) : "f"(x));
    return y;
}
__device__ __forceinline__ float sig_apx(float x) {
    return fmaf(tanh_apx(0.5f * x), 0.5f, 0.5f);   // 1 MUFU
}

__global__ void __launch_bounds__(256, 2)
enc_kernel(const float* __restrict__ x,
           const float* __restrict__ Wih,
           const float* __restrict__ Whh,
           const float* __restrict__ bih,
           const float* __restrict__ bhh)
{
    __shared__ __align__(16) float h_s[65 * BB];     // [k][b]; k=64 row = x_t
    __shared__ float gbuf[BB * GATES];               // gate exchange [b][g]

    const int tid   = threadIdx.x;
    const int bbase = blockIdx.x * BB;
    const int g     = tid;

    // ---- time-invariant weights in registers (65 scalars) ----
    float Wr[65];
#pragma unroll
    for (int k = 0; k < 64; k++) Wr[k] = Whh[g * 64 + k];
    Wr[64] = Wih[g];                       // x contribution (IN = 1)
    const float bias = bih[g] + bhh[g];

    // ---- zero h state ----
    for (int i = tid; i < 65 * BB; i += 256) h_s[i] = 0.0f;

    const int j = tid & 63;      // epilogue cell index
    const int b = tid >> 6;      // epilogue batch row (0..3)
    float c = 0.0f;              // cell state for (j, b)

    // prefetch x for t=0
    float xr = 0.0f;
    if (tid < BB) xr = x[bbase + tid];

    __syncthreads();

    for (int t = 0; t < T_STEPS; t++) {
        if (tid < BB) h_s[64 * BB + tid] = xr;   // stage x_t
        __syncthreads();   // orders prev epilogue h writes + x before reads

        // prefetch next x while the gate loop runs (hides LDG latency)
        if (tid < BB && t + 1 < T_STEPS) xr = x[(t + 1) * BATCH + bbase + tid];

        // ---- gates[b][g] = sum_k h[k][b]*Wr[k]; 1 LDS.128 + 4 FFMA per k
        float a0 = bias, a1 = bias, a2 = bias, a3 = bias;
#pragma unroll
        for (int k = 0; k < 65; k++) {
            const float4 hv = *(const float4*)(h_s + k * BB);   // broadcast
            const float w = Wr[k];
            a0 = fmaf(w, hv.x, a0);
            a1 = fmaf(w, hv.y, a1);
            a2 = fmaf(w, hv.z, a2);
            a3 = fmaf(w, hv.w, a3);
        }

        gbuf[0 * GATES + g] = a0;
        gbuf[1 * GATES + g] = a1;
        gbuf[2 * GATES + g] = a2;
        gbuf[3 * GATES + g] = a3;
        __syncthreads();

        // ---- LSTM cell epilogue: one (cell, row) per thread, 5 MUFU total
        {
            const float* gb = gbuf + b * GATES;
            const float i_ = sig_apx(gb[j]);
            const float f_ = sig_apx(gb[64 + j]);
            const float G_ = tanh_apx(gb[128 + j]);
            const float o_ = sig_apx(gb[192 + j]);
            c = fmaf(f_, c, i_ * G_);
            h_s[j * BB + b] = o_ * tanh_apx(c);
        }
        // next iteration's top barrier provides the ordering
    }

    __syncthreads();
    // ---- export final h (transposed [k][b]) for the decoder ----
    if (tid < HID * BB) {
        const int k = tid >> 2;
        const int bb = tid & 3;
        g_henc[k * BATCH + bbase + bb] = h_s[k * BB + bb];
    }
}

__global__ void __launch_bounds__(32)
dec_kernel(const float* __restrict__ Wih,
           const float* __restrict__ Whh,
           const float* __restrict__ bih,
           const float* __restrict__ bhh,
           float* __restrict__ out)
{
    const int b = blockIdx.x * 32 + threadIdx.x;

    // z[g] = h_enc[b] . Wih_d[g] + bias  (constant across decoder steps)
    float z0 = bih[0] + bhh[0];
    float z1 = bih[1] + bhh[1];
    float z2 = bih[2] + bhh[2];
    float z3 = bih[3] + bhh[3];
#pragma unroll 8
    for (int k = 0; k < HID; k++) {
        const float hv = g_henc[k * BATCH + b];   // coalesced
        z0 = fmaf(hv, Wih[0 * HID + k], z0);
        z1 = fmaf(hv, Wih[1 * HID + k], z1);
        z2 = fmaf(hv, Wih[2 * HID + k], z2);
        z3 = fmaf(hv, Wih[3 * HID + k], z3);
    }
    const float w0 = Whh[0], w1 = Whh[1], w2 = Whh[2], w3 = Whh[3];

    float h = 0.0f, c = 0.0f;
    for (int t = 0; t < T_STEPS; t++) {
        const float i_ = sig_apx(fmaf(h, w0, z0));
        const float f_ = sig_apx(fmaf(h, w1, z1));
        const float G_ = tanh_apx(fmaf(h, w2, z2));
        const float o_ = sig_apx(fmaf(h, w3, z3));
        c = fmaf(f_, c, i_ * G_);
        h = o_ * tanh_apx(c);
        out[t * BATCH + b] = h;   // coalesced
    }
}

extern "C" void kernel_launch(void* const* d_in, const int* in_sizes, int n_in,
                              void* d_out, int out_size)
{
    const float* x     = (const float*)d_in[0];
    const float* Wih_e = (const float*)d_in[1];
    const float* Whh_e = (const float*)d_in[2];
    const float* bih_e = (const float*)d_in[3];
    const float* bhh_e = (const float*)d_in[4];
    const float* Wih_d = (const float*)d_in[5];
    const float* Whh_d = (const float*)d_in[6];
    const float* bih_d = (const float*)d_in[7];
    const float* bhh_d = (const float*)d_in[8];

    enc_kernel<<<BATCH / BB, 256>>>(x, Wih_e, Whh_e, bih_e, bhh_e);
    dec_kernel<<<BATCH / 32, 32>>>(Wih_d, Whh_d, bih_d, bhh_d, (float*)d_out);
}

// round 15
// speedup vs baseline: 2.6220x; 2.6220x over previous
#include <cuda_runtime.h>
#include <cstdint>

// LSTM autoencoder: T=1024, B=1024, IN=1, H=64
// R5 finding: FFMA-3reg is rt_SMSP=2 on sm_103a -> scalar encoder is hard-capped
// at 64 MACs/cyc/SM (~1.1ms). Move the step GEMM to tensor cores:
//   128 blocks (1/SM) x 256 threads, BB=8 batch rows/block.
//   Per step: gates[256,8] = Whh[256,64] @ h[64,8] via mma.sync.m16n8k8.tf32.
//   Weights live in A-fragments in registers (loaded once, tf32-rounded).
//   h kept tf32-rounded in SMEM [k][b] stride 8 (conflict-free B-frag loads).
//   Epilogue: MUFU.TANH activations, c state fp32 in regs.

#define T_STEPS 1024
#define BATCH   1024
#define HID     64
#define GATES   256
#define BB      8
#define GSTRIDE 260        // gbuf row stride (floats): conflict-free STS+LDS

__device__ float g_henc[HID * BATCH];   // h_enc transposed: [k][b]

__device__ __forceinline__ float tanh_apx(float x) {
    float y;
    asm("tanh.approx.f32 %0, %1;" : "=f"(y) : "f"(x));
    return y;
}
__device__ __forceinline__ float sig_apx(float x) {
    return fmaf(tanh_apx(0.5f * x), 0.5f, 0.5f);   // 1 MUFU
}
__device__ __forceinline__ uint32_t to_tf32(float f) {
    uint32_t u;
    asm("cvt.rna.tf32.f32 %0, %1;" : "=r"(u) : "f"(f));
    return u;
}
__device__ __forceinline__ void mma_tf32(float& c0, float& c1, float& c2, float& c3,
                                         uint32_t a0, uint32_t a1, uint32_t a2, uint32_t a3,
                                         uint32_t b0, uint32_t b1) {
    asm volatile("mma.sync.aligned.m16n8k8.row.col.f32.tf32.tf32.f32 "
                 "{%0,%1,%2,%3},{%4,%5,%6,%7},{%8,%9},{%0,%1,%2,%3};"
                 : "+f"(c0), "+f"(c1), "+f"(c2), "+f"(c3)
                 : "r"(a0), "r"(a1), "r"(a2), "r"(a3), "r"(b0), "r"(b1));
}

__global__ void __launch_bounds__(256, 1)
enc_kernel(const float* __restrict__ x,
           const float* __restrict__ Wih,
           const float* __restrict__ Whh,
           const float* __restrict__ bih,
           const float* __restrict__ bhh)
{
    __shared__ __align__(16) float h_s[HID * BB];   // [k][b], stride 8 (tf32 vals)
    __shared__ float x_s[BB];
    __shared__ float gbuf[BB * GSTRIDE];            // [b][g], padded

    const int tid   = threadIdx.x;
    const int warp  = tid >> 5;
    const int lane  = tid & 31;
    const int gid   = lane >> 2;       // group id (0..7)
    const int tig   = lane & 3;        // thread in group
    const int bbase = blockIdx.x * BB;

    // ---- A fragments: Whh rows [warp*32, warp*32+32), tf32, resident ----
    // m16n8k8 A layout: a0:(gid,tig) a1:(gid+8,tig) a2:(gid,tig+4) a3:(gid+8,tig+4)
    uint32_t A[2][8][4];
    const int gbase = warp * 32;
#pragma unroll
    for (int gm = 0; gm < 2; gm++)
#pragma unroll
        for (int ks = 0; ks < 8; ks++) {
            const int r0 = gbase + gm * 16 + gid;
            const int k0 = ks * 8 + tig;
            A[gm][ks][0] = to_tf32(Whh[r0 * HID + k0]);
            A[gm][ks][1] = to_tf32(Whh[(r0 + 8) * HID + k0]);
            A[gm][ks][2] = to_tf32(Whh[r0 * HID + k0 + 4]);
            A[gm][ks][3] = to_tf32(Whh[(r0 + 8) * HID + k0 + 4]);
        }

    // ---- epilogue constants: thread -> cell j, batch rows bq, bq+4 ----
    const int j  = tid & 63;
    const int bq = tid >> 6;
    const float wi = Wih[j],        wf = Wih[64 + j];
    const float wg = Wih[128 + j],  wo = Wih[192 + j];
    const float bi = bih[j] + bhh[j];
    const float bf = bih[64 + j] + bhh[64 + j];
    const float bg = bih[128 + j] + bhh[128 + j];
    const float bo = bih[192 + j] + bhh[192 + j];
    float cs[2] = {0.0f, 0.0f};

    for (int i = tid; i < HID * BB; i += 256) h_s[i] = 0.0f;
    float xr = 0.0f;
    if (tid < BB) xr = x[bbase + tid];
    __syncthreads();

    const uint32_t* hu = (const uint32_t*)h_s;

    for (int t = 0; t < T_STEPS; t++) {
        // ---- MMA phase: 16 mma, 4 acc sets (gm x k-half) to shorten chains
        float acc[4][4];
#pragma unroll
        for (int s = 0; s < 4; s++) { acc[s][0]=0.f; acc[s][1]=0.f; acc[s][2]=0.f; acc[s][3]=0.f; }
#pragma unroll
        for (int ks = 0; ks < 8; ks++) {
            // B frag (col-major KxN): b0:(k=tig, n=gid) b1:(k=tig+4, n=gid)
            const uint32_t b0 = hu[ks * 64 + tig * 8 + gid];
            const uint32_t b1 = hu[ks * 64 + tig * 8 + 32 + gid];
            const int kh = ks >> 2;
            mma_tf32(acc[kh][0], acc[kh][1], acc[kh][2], acc[kh][3],
                     A[0][ks][0], A[0][ks][1], A[0][ks][2], A[0][ks][3], b0, b1);
            mma_tf32(acc[2+kh][0], acc[2+kh][1], acc[2+kh][2], acc[2+kh][3],
                     A[1][ks][0], A[1][ks][1], A[1][ks][2], A[1][ks][3], b0, b1);
        }

        // stage x_t (read in this step's epilogue), prefetch x[t+1]
        if (tid < BB) x_s[tid] = xr;
        if (tid < BB && t + 1 < T_STEPS) xr = x[(t + 1) * BATCH + bbase + tid];

        // ---- scatter gates to gbuf [b][g]
        // C frag: c0:(m=gid,n=2tig) c1:(m=gid,n=2tig+1) c2:(m=gid+8,..) c3:(m=gid+8,..)
        {
            const int g0  = gbase + gid;
            const int co0 = (tig * 2) * GSTRIDE;
            const int co1 = co0 + GSTRIDE;
            gbuf[co0 + g0]      = acc[0][0] + acc[1][0];
            gbuf[co1 + g0]      = acc[0][1] + acc[1][1];
            gbuf[co0 + g0 + 8]  = acc[0][2] + acc[1][2];
            gbuf[co1 + g0 + 8]  = acc[0][3] + acc[1][3];
            gbuf[co0 + g0 + 16] = acc[2][0] + acc[3][0];
            gbuf[co1 + g0 + 16] = acc[2][1] + acc[3][1];
            gbuf[co0 + g0 + 24] = acc[2][2] + acc[3][2];
            gbuf[co1 + g0 + 24] = acc[2][3] + acc[3][3];
        }
        __syncthreads();

        // ---- LSTM epilogue: thread handles (cell j, b=bq) and (j, b=bq+4)
#pragma unroll
        for (int q = 0; q < 2; q++) {
            const int b = bq + q * 4;
            const float xb = x_s[b];
            const float* gb = gbuf + b * GSTRIDE;
            const float gi = fmaf(wi, xb, gb[j] + bi);
            const float gf = fmaf(wf, xb, gb[64 + j] + bf);
            const float gg = fmaf(wg, xb, gb[128 + j] + bg);
            const float go = fmaf(wo, xb, gb[192 + j] + bo);
            const float i_ = sig_apx(gi);
            const float f_ = sig_apx(gf);
            const float G_ = tanh_apx(gg);
            const float o_ = sig_apx(go);
            cs[q] = fmaf(f_, cs[q], i_ * G_);
            const float hn = o_ * tanh_apx(cs[q]);
            h_s[j * 8 + b] = __uint_as_float(to_tf32(hn));  // tf32-consistent state
        }
        __syncthreads();   // h_s ready for next step's B-frag loads
    }

    // ---- export final h (transposed [k][b]) for the decoder ----
#pragma unroll
    for (int q = 0; q < 2; q++) {
        const int idx = tid + q * 256;      // 512 = 64*8 entries
        const int k = idx >> 3;
        const int b = idx & 7;
        g_henc[k * BATCH + bbase + b] = h_s[idx];
    }
}

__global__ void __launch_bounds__(32)
dec_kernel(const float* __restrict__ Wih,
           const float* __restrict__ Whh,
           const float* __restrict__ bih,
           const float* __restrict__ bhh,
           float* __restrict__ out)
{
    const int b = blockIdx.x * 32 + threadIdx.x;

    float z0 = bih[0] + bhh[0];
    float z1 = bih[1] + bhh[1];
    float z2 = bih[2] + bhh[2];
    float z3 = bih[3] + bhh[3];
#pragma unroll 8
    for (int k = 0; k < HID; k++) {
        const float hv = g_henc[k * BATCH + b];   // coalesced
        z0 = fmaf(hv, Wih[0 * HID + k], z0);
        z1 = fmaf(hv, Wih[1 * HID + k], z1);
        z2 = fmaf(hv, Wih[2 * HID + k], z2);
        z3 = fmaf(hv, Wih[3 * HID + k], z3);
    }
    const float w0 = Whh[0], w1 = Whh[1], w2 = Whh[2], w3 = Whh[3];

    float h = 0.0f, c = 0.0f;
    for (int t = 0; t < T_STEPS; t++) {
        const float i_ = sig_apx(fmaf(h, w0, z0));
        const float f_ = sig_apx(fmaf(h, w1, z1));
        const float G_ = tanh_apx(fmaf(h, w2, z2));
        const float o_ = sig_apx(fmaf(h, w3, z3));
        c = fmaf(f_, c, i_ * G_);
        h = o_ * tanh_apx(c);
        out[t * BATCH + b] = h;   // coalesced
    }
}

extern "C" void kernel_launch(void* const* d_in, const int* in_sizes, int n_in,
                              void* d_out, int out_size)
{
    const float* x     = (const float*)d_in[0];
    const float* Wih_e = (const float*)d_in[1];
    const float* Whh_e = (const float*)d_in[2];
    const float* bih_e = (const float*)d_in[3];
    const float* bhh_e = (const float*)d_in[4];
    const float* Wih_d = (const float*)d_in[5];
    const float* Whh_d = (const float*)d_in[6];
    const float* bih_d = (const float*)d_in[7];
    const float* bhh_d = (const float*)d_in[8];

    enc_kernel<<<BATCH / BB, 256>>>(x, Wih_e, Whh_e, bih_e, bhh_e);
    dec_kernel<<<BATCH / 32, 32>>>(Wih_d, Whh_d, bih_d, bhh_d, (float*)d_out);
}